// round 12
// baseline (speedup 1.0000x reference)
#include <cuda_runtime.h>
#include <cuda_fp16.h>
#include <cstdint>

// ---------------- problem constants ----------------
static constexpr int BATCH = 4096;
static constexpr int IN_SZ = 1024;
static constexpr int HID   = 2048;
static constexpr int KDIM  = 3072;   // IN_SZ + HID
static constexpr int NDIM  = 8192;   // 4*HID, gate-interleaved rows: n = 4*h + gate

// ---------------- GEMM tiling ----------------
static constexpr int BM = 128;
static constexpr int BN = 128;
static constexpr int BK = 64;
static constexpr int KITERS = KDIM / BK;     // 48
static constexpr int STAGES = 3;
static constexpr int TILE_BYTES = 128 * 64 * 2;       // 16 KB
static constexpr int STAGE_BYTES = 2 * TILE_BYTES;    // 32 KB
static constexpr int SMEM_CTRL = 1024;
static constexpr int SMEM_TOTAL = SMEM_CTRL + STAGES * STAGE_BYTES;  // 99328

// ---------------- device scratch: PRE-TILED + PRE-SWIZZLED ----------------
__device__ __align__(1024) __half g_A[(size_t)BATCH * KDIM];   // 25 MB
__device__ __align__(1024) __half g_W[(size_t)NDIM * KDIM];    // 50 MB
__device__ float  g_bias[NDIM];

// ---------------- helpers ----------------
__device__ __forceinline__ uint32_t smem_u32(const void* p) {
    uint32_t a;
    asm("{ .reg .u64 t; cvta.to.shared.u64 t, %1; cvt.u32.u64 %0, t; }" : "=r"(a) : "l"(p));
    return a;
}
__device__ __forceinline__ uint32_t swz128(uint32_t off) {
    return off ^ ((off >> 3) & 0x70);
}
__device__ __forceinline__ void mbar_init(uint32_t a, uint32_t cnt) {
    asm volatile("mbarrier.init.shared.b64 [%0], %1;" :: "r"(a), "r"(cnt) : "memory");
}
__device__ __forceinline__ void mbar_arrive(uint32_t a) {
    asm volatile("mbarrier.arrive.shared.b64 _, [%0];" :: "r"(a) : "memory");
}
__device__ __forceinline__ void mbar_expect_tx(uint32_t a, uint32_t bytes) {
    asm volatile("mbarrier.arrive.expect_tx.shared.b64 _, [%0], %1;"
                 :: "r"(a), "r"(bytes) : "memory");
}
__device__ __forceinline__ void mbar_wait(uint32_t mbar, uint32_t parity) {
    uint32_t done;
    do {
        asm volatile("{\n\t.reg .pred p;\n\t"
            "mbarrier.try_wait.parity.acquire.cta.shared::cta.b64 p, [%1], %2, 0x989680;\n\t"
            "selp.b32 %0, 1, 0, p;\n\t}"
            : "=r"(done) : "r"(mbar), "r"(parity) : "memory");
    } while (!done);
}
__device__ __forceinline__ void bulk_ldgsts(uint32_t dst, const void* src,
                                            uint32_t bytes, uint32_t mbar) {
    asm volatile("cp.async.bulk.shared::cluster.global.mbarrier::complete_tx::bytes "
                 "[%0], [%1], %2, [%3];"
                 :: "r"(dst), "l"(src), "r"(bytes), "r"(mbar) : "memory");
}
__device__ __forceinline__ void ldsm4(uint32_t* r, uint32_t addr) {
    asm volatile("ldmatrix.sync.aligned.m8n8.x4.shared.b16 {%0,%1,%2,%3}, [%4];"
                 : "=r"(r[0]), "=r"(r[1]), "=r"(r[2]), "=r"(r[3]) : "r"(addr));
}
__device__ __forceinline__ void mma16816(float* c, const uint32_t* a, uint32_t b0, uint32_t b1) {
    asm volatile("mma.sync.aligned.m16n8k16.row.col.f32.f16.f16.f32 "
                 "{%0,%1,%2,%3}, {%4,%5,%6,%7}, {%8,%9}, {%0,%1,%2,%3};"
                 : "+f"(c[0]), "+f"(c[1]), "+f"(c[2]), "+f"(c[3])
                 : "r"(a[0]), "r"(a[1]), "r"(a[2]), "r"(a[3]), "r"(b0), "r"(b1));
}
__device__ __forceinline__ float sigmoidf_(float x) { return 1.f / (1.f + __expf(-x)); }
__device__ __forceinline__ float tanhf_(float x)    { return 2.f / (1.f + __expf(-2.f * x)) - 1.f; }

// ---------------- merged conversion: fp32 -> fp16, tiled + swizzled (R8) ----------------
static constexpr int A_CHUNKS = BATCH * KDIM / 4;
static constexpr int W_CHUNKS = NDIM * KDIM / 4;
static constexpr int TOT_CHUNKS = A_CHUNKS + W_CHUNKS;

__global__ void __launch_bounds__(256) convert_all_kernel(
    const float* __restrict__ x, const float* __restrict__ h,
    const float* __restrict__ W0, const float* __restrict__ W1,
    const float* __restrict__ W2, const float* __restrict__ W3,
    const float* __restrict__ bb0, const float* __restrict__ bb1,
    const float* __restrict__ bb2, const float* __restrict__ bb3) {
    int idx = blockIdx.x * blockDim.x + threadIdx.x;
    if (idx >= TOT_CHUNKS) return;
    if (idx < A_CHUNKS) {
        int b   = idx / (KDIM / 4);
        int col = (idx - b * (KDIM / 4)) * 4;
        float4 v;
        if (col < IN_SZ) v = *(const float4*)(x + (size_t)b * IN_SZ + col);
        else             v = *(const float4*)(h + (size_t)b * HID + (col - IN_SZ));
        __half2 lo = __floats2half2_rn(v.x, v.y);
        __half2 hi = __floats2half2_rn(v.z, v.w);
        uint2 pk = make_uint2(*reinterpret_cast<uint32_t*>(&lo), *reinterpret_cast<uint32_t*>(&hi));
        int tm = b >> 7, row = b & 127;
        int kt = col >> 6, c = col & 63;
        size_t off = (size_t)(tm * KITERS + kt) * TILE_BYTES + swz128(row * 128 + c * 2);
        *reinterpret_cast<uint2*>(reinterpret_cast<char*>(g_A) + off) = pk;
    } else {
        int widx = idx - A_CHUNKS;
        int n   = widx / (KDIM / 4);
        int c4  = widx - n * (KDIM / 4);
        int col = c4 * 4;
        int g = n & 3, hh = n >> 2;
        const float* W = (g == 0) ? W0 : (g == 1) ? W1 : (g == 2) ? W2 : W3;
        float4 v = *(const float4*)(W + (size_t)hh * KDIM + col);
        __half2 lo = __floats2half2_rn(v.x, v.y);
        __half2 hi = __floats2half2_rn(v.z, v.w);
        uint2 pk = make_uint2(*reinterpret_cast<uint32_t*>(&lo), *reinterpret_cast<uint32_t*>(&hi));
        int tn = n >> 7, row = n & 127;
        int kt = col >> 6, c = col & 63;
        size_t off = (size_t)(tn * KITERS + kt) * TILE_BYTES + swz128(row * 128 + c * 2);
        *reinterpret_cast<uint2*>(reinterpret_cast<char*>(g_W) + off) = pk;
        if (c4 == 0) {
            const float* bp = (g == 0) ? bb0 : (g == 1) ? bb1 : (g == 2) ? bb2 : bb3;
            g_bias[n] = bp[hh];
        }
    }
}

// ---------------- fused GEMM + LSTM kernel: dedicated DMA-producer warp ----------------
// 288 threads: warps 0-7 = consumers (4M x 2N, 32x64 tiles), warp 8 lane 0 = producer.
// All empty-waits live in the producer warp; consumer loop is pure
// full-wait -> LDSM -> MMA -> arrive. No convoy on the consumer critical path.
__global__ void __launch_bounds__(288, 2) lstm_gemm_kernel(const float* __restrict__ c_prev,
                                                           float* __restrict__ out) {
    extern __shared__ char smem[];
    const uint32_t sbase = smem_u32(smem);
    float* bias_sm = reinterpret_cast<float*>(smem);             // 512 B
    float* EP      = reinterpret_cast<float*>(smem + SMEM_CTRL); // epilogue staging, 64 KB

    const int tid  = threadIdx.x;
    const int wid  = tid >> 5;
    const int lane = tid & 31;
    const int m0 = blockIdx.y * BM;
    const int n0 = blockIdx.x * BN;

    const uint32_t mb = sbase + 512;
    auto full_b  = [&](int s) { return mb + s * 16; };
    auto empty_b = [&](int s) { return mb + s * 16 + 8; };

    if (tid == 0) {
        for (int s = 0; s < STAGES; s++) {
            mbar_init(full_b(s), 1);    // producer's expect_tx arrival
            mbar_init(empty_b(s), 8);   // one arrive per consumer warp
        }
        asm volatile("fence.proxy.async.shared::cta;" ::: "memory");
    }
    if (tid < BN) bias_sm[tid] = g_bias[n0 + tid];
    __syncthreads();

    if (wid == 8) {
        // ================= producer (warp 8, lane 0) =================
        if (lane == 0) {
            const char* Abase = reinterpret_cast<const char*>(g_A)
                              + (size_t)blockIdx.y * KITERS * TILE_BYTES;
            const char* Bbase = reinterpret_cast<const char*>(g_W)
                              + (size_t)blockIdx.x * KITERS * TILE_BYTES;
            for (int kp = 0; kp < KITERS; kp++) {
                if (kp >= STAGES)
                    mbar_wait(empty_b(kp % STAGES), ((kp / STAGES) + 1) & 1);
                const int s2 = kp % STAGES;
                mbar_expect_tx(full_b(s2), STAGE_BYTES);
                const uint32_t a_s = sbase + SMEM_CTRL + s2 * STAGE_BYTES;
                bulk_ldgsts(a_s,              Abase + (size_t)kp * TILE_BYTES,
                            TILE_BYTES, full_b(s2));
                bulk_ldgsts(a_s + TILE_BYTES, Bbase + (size_t)kp * TILE_BYTES,
                            TILE_BYTES, full_b(s2));
            }
        }
        __syncthreads();   // join consumers before EP overlay
        __syncthreads();
        return;            // producer skips pointwise
    }

    // ================= consumers (warps 0-7) =================
    const int warp_m = wid & 3;
    const int warp_n = wid >> 2;
    const int lrow  = lane & 15;
    const int lkoff = (lane >> 4) * 16;

    uint32_t aoff[2], boff[4];
#pragma unroll
    for (int mt = 0; mt < 2; mt++)
        aoff[mt] = swz128((warp_m * 32 + mt * 16 + lrow) * 128 + lkoff);
#pragma unroll
    for (int nt2 = 0; nt2 < 4; nt2++)
        boff[nt2] = swz128((warp_n * 64 + nt2 * 16 + lrow) * 128 + lkoff);

    float acc[2][8][4];
#pragma unroll
    for (int mt = 0; mt < 2; mt++)
#pragma unroll
        for (int nt = 0; nt < 8; nt++)
#pragma unroll
            for (int q = 0; q < 4; q++) acc[mt][nt][q] = 0.f;

    int s = 0; uint32_t phf = 0;
    for (int k = 0; k < KITERS; k++) {
        mbar_wait(full_b(s), phf);
        const uint32_t a_s = sbase + SMEM_CTRL + s * STAGE_BYTES;
        const uint32_t b_s = a_s + TILE_BYTES;
#pragma unroll
        for (int ks = 0; ks < 4; ks++) {
            const uint32_t kx = ks * 32;
            uint32_t af[2][4];
#pragma unroll
            for (int mt = 0; mt < 2; mt++) ldsm4(af[mt], a_s + (aoff[mt] ^ kx));
            uint32_t bf[4][4];
#pragma unroll
            for (int nt2 = 0; nt2 < 4; nt2++) ldsm4(bf[nt2], b_s + (boff[nt2] ^ kx));
#pragma unroll
            for (int mt = 0; mt < 2; mt++)
#pragma unroll
                for (int nt = 0; nt < 8; nt++)
                    mma16816(acc[mt][nt], af[mt],
                             bf[nt >> 1][nt & 1], bf[nt >> 1][2 + (nt & 1)]);
        }
        if (lane == 0) mbar_arrive(empty_b(s));   // LDSM data is in registers
        if (++s == STAGES) { s = 0; phf ^= 1; }
    }

    // -------- epilogue: stage accum to SMEM, then fused LSTM pointwise --------
    __syncthreads();   // all warps done with stage SMEM; EP overlays it

    const int g4 = lane >> 2;
    const int t4 = lane & 3;
#pragma unroll
    for (int mt = 0; mt < 2; mt++) {
#pragma unroll
        for (int nt = 0; nt < 8; nt++) {
            int row = warp_m * 32 + mt * 16 + g4;
            int col = warp_n * 64 + nt * 8 + 2 * t4;
            *reinterpret_cast<float2*>(&EP[row * BN + col]) =
                make_float2(acc[mt][nt][0], acc[mt][nt][1]);
            *reinterpret_cast<float2*>(&EP[(row + 8) * BN + col]) =
                make_float2(acc[mt][nt][2], acc[mt][nt][3]);
        }
    }
    __syncthreads();

    const int h0 = n0 >> 2;                       // 32 hidden units per CTA
    float* h_out = out;
    float* c_out = out + (size_t)BATCH * HID;
#pragma unroll
    for (int it = 0; it < (BM * (BN / 4)) / 256; it++) {
        int cell = it * 256 + tid;
        int ml = cell >> 5;
        int hl = cell & 31;
        float4 gv = *reinterpret_cast<float4*>(&EP[ml * BN + 4 * hl]);
        float4 bv = *reinterpret_cast<float4*>(&bias_sm[4 * hl]);
        float it_g = sigmoidf_(gv.x + bv.x);
        float ft   = sigmoidf_(gv.y + bv.y);
        float gt   = tanhf_(gv.z + bv.z);
        float ot   = sigmoidf_(gv.w + bv.w);
        int m = m0 + ml;
        int h = h0 + hl;
        float ct = ft * c_prev[(size_t)m * HID + h] + it_g * gt;
        h_out[(size_t)m * HID + h] = ot * tanhf_(ct);
        c_out[(size_t)m * HID + h] = ct;
    }
}

// ---------------- launch ----------------
extern "C" void kernel_launch(void* const* d_in, const int* in_sizes, int n_in,
                              void* d_out, int out_size) {
    const float* x_t    = (const float*)d_in[0];
    const float* h_prev = (const float*)d_in[1];
    const float* c_prev = (const float*)d_in[2];
    const float* W_i = (const float*)d_in[3];
    const float* b_i = (const float*)d_in[4];
    const float* W_f = (const float*)d_in[5];
    const float* b_f = (const float*)d_in[6];
    const float* W_c = (const float*)d_in[7];
    const float* b_c = (const float*)d_in[8];
    const float* W_o = (const float*)d_in[9];
    const float* b_o = (const float*)d_in[10];
    float* out = (float*)d_out;

    cudaFuncSetAttribute(lstm_gemm_kernel,
                         cudaFuncAttributeMaxDynamicSharedMemorySize, SMEM_TOTAL);

    convert_all_kernel<<<(TOT_CHUNKS + 255) / 256, 256>>>(
        x_t, h_prev, W_i, W_f, W_c, W_o, b_i, b_f, b_c, b_o);
    dim3 grid(NDIM / BN, BATCH / BM);  // 64 x 32
    lstm_gemm_kernel<<<grid, 288, SMEM_TOTAL>>>(c_prev, out);
}

// round 14
// speedup vs baseline: 1.6273x; 1.6273x over previous
#include <cuda_runtime.h>
#include <cuda_fp16.h>
#include <cstdint>

// ---------------- problem constants ----------------
static constexpr int BATCH = 4096;
static constexpr int IN_SZ = 1024;
static constexpr int HID   = 2048;
static constexpr int KDIM  = 3072;   // IN_SZ + HID
static constexpr int NDIM  = 8192;   // 4*HID, gate-interleaved rows: n = 4*h + gate

// ---------------- GEMM tiling ----------------
static constexpr int BM = 128;
static constexpr int BN = 128;
static constexpr int BK = 64;
static constexpr int KITERS = KDIM / BK;     // 48
static constexpr int STAGES = 3;
static constexpr int TILE_BYTES = 128 * 64 * 2;       // 16 KB
static constexpr int STAGE_BYTES = 2 * TILE_BYTES;    // 32 KB
static constexpr int SMEM_CTRL = 1024;
static constexpr int SMEM_TOTAL = SMEM_CTRL + STAGES * STAGE_BYTES;  // 99328

// ---------------- device scratch: PRE-TILED + PRE-SWIZZLED ----------------
__device__ __align__(1024) __half g_A[(size_t)BATCH * KDIM];   // 25 MB
__device__ __align__(1024) __half g_W[(size_t)NDIM * KDIM];    // 50 MB
__device__ float  g_bias[NDIM];

// ---------------- helpers ----------------
__device__ __forceinline__ uint32_t smem_u32(const void* p) {
    uint32_t a;
    asm("{ .reg .u64 t; cvta.to.shared.u64 t, %1; cvt.u32.u64 %0, t; }" : "=r"(a) : "l"(p));
    return a;
}
__device__ __forceinline__ uint32_t swz128(uint32_t off) {
    return off ^ ((off >> 3) & 0x70);
}
__device__ __forceinline__ void mbar_init(uint32_t a, uint32_t cnt) {
    asm volatile("mbarrier.init.shared.b64 [%0], %1;" :: "r"(a), "r"(cnt) : "memory");
}
__device__ __forceinline__ void mbar_arrive(uint32_t a) {
    asm volatile("mbarrier.arrive.shared.b64 _, [%0];" :: "r"(a) : "memory");
}
__device__ __forceinline__ void mbar_expect_tx(uint32_t a, uint32_t bytes) {
    asm volatile("mbarrier.arrive.expect_tx.shared.b64 _, [%0], %1;"
                 :: "r"(a), "r"(bytes) : "memory");
}
__device__ __forceinline__ void mbar_wait(uint32_t mbar, uint32_t parity) {
    uint32_t done;
    do {
        asm volatile("{\n\t.reg .pred p;\n\t"
            "mbarrier.try_wait.parity.acquire.cta.shared::cta.b64 p, [%1], %2, 0x989680;\n\t"
            "selp.b32 %0, 1, 0, p;\n\t}"
            : "=r"(done) : "r"(mbar), "r"(parity) : "memory");
    } while (!done);
}
__device__ __forceinline__ void bulk_ldgsts(uint32_t dst, const void* src,
                                            uint32_t bytes, uint32_t mbar) {
    asm volatile("cp.async.bulk.shared::cluster.global.mbarrier::complete_tx::bytes "
                 "[%0], [%1], %2, [%3];"
                 :: "r"(dst), "l"(src), "r"(bytes), "r"(mbar) : "memory");
}
__device__ __forceinline__ void ldsm4(uint32_t* r, uint32_t addr) {
    asm volatile("ldmatrix.sync.aligned.m8n8.x4.shared.b16 {%0,%1,%2,%3}, [%4];"
                 : "=r"(r[0]), "=r"(r[1]), "=r"(r[2]), "=r"(r[3]) : "r"(addr));
}
__device__ __forceinline__ void mma16816(float* c, const uint32_t* a, uint32_t b0, uint32_t b1) {
    asm volatile("mma.sync.aligned.m16n8k16.row.col.f32.f16.f16.f32 "
                 "{%0,%1,%2,%3}, {%4,%5,%6,%7}, {%8,%9}, {%0,%1,%2,%3};"
                 : "+f"(c[0]), "+f"(c[1]), "+f"(c[2]), "+f"(c[3])
                 : "r"(a[0]), "r"(a[1]), "r"(a[2]), "r"(a[3]), "r"(b0), "r"(b1));
}
__device__ __forceinline__ float sigmoidf_(float x) { return 1.f / (1.f + __expf(-x)); }
__device__ __forceinline__ float tanhf_(float x)    { return 2.f / (1.f + __expf(-2.f * x)) - 1.f; }

// ---------------- merged conversion: fp32 -> fp16, tiled + swizzled (R8) ----------------
static constexpr int A_CHUNKS = BATCH * KDIM / 4;
static constexpr int W_CHUNKS = NDIM * KDIM / 4;
static constexpr int TOT_CHUNKS = A_CHUNKS + W_CHUNKS;

__global__ void __launch_bounds__(256) convert_all_kernel(
    const float* __restrict__ x, const float* __restrict__ h,
    const float* __restrict__ W0, const float* __restrict__ W1,
    const float* __restrict__ W2, const float* __restrict__ W3,
    const float* __restrict__ bb0, const float* __restrict__ bb1,
    const float* __restrict__ bb2, const float* __restrict__ bb3) {
    int idx = blockIdx.x * blockDim.x + threadIdx.x;
    if (idx >= TOT_CHUNKS) return;
    if (idx < A_CHUNKS) {
        int b   = idx / (KDIM / 4);
        int col = (idx - b * (KDIM / 4)) * 4;
        float4 v;
        if (col < IN_SZ) v = *(const float4*)(x + (size_t)b * IN_SZ + col);
        else             v = *(const float4*)(h + (size_t)b * HID + (col - IN_SZ));
        __half2 lo = __floats2half2_rn(v.x, v.y);
        __half2 hi = __floats2half2_rn(v.z, v.w);
        uint2 pk = make_uint2(*reinterpret_cast<uint32_t*>(&lo), *reinterpret_cast<uint32_t*>(&hi));
        int tm = b >> 7, row = b & 127;
        int kt = col >> 6, c = col & 63;
        size_t off = (size_t)(tm * KITERS + kt) * TILE_BYTES + swz128(row * 128 + c * 2);
        *reinterpret_cast<uint2*>(reinterpret_cast<char*>(g_A) + off) = pk;
    } else {
        int widx = idx - A_CHUNKS;
        int n   = widx / (KDIM / 4);
        int c4  = widx - n * (KDIM / 4);
        int col = c4 * 4;
        int g = n & 3, hh = n >> 2;
        const float* W = (g == 0) ? W0 : (g == 1) ? W1 : (g == 2) ? W2 : W3;
        float4 v = *(const float4*)(W + (size_t)hh * KDIM + col);
        __half2 lo = __floats2half2_rn(v.x, v.y);
        __half2 hi = __floats2half2_rn(v.z, v.w);
        uint2 pk = make_uint2(*reinterpret_cast<uint32_t*>(&lo), *reinterpret_cast<uint32_t*>(&hi));
        int tn = n >> 7, row = n & 127;
        int kt = col >> 6, c = col & 63;
        size_t off = (size_t)(tn * KITERS + kt) * TILE_BYTES + swz128(row * 128 + c * 2);
        *reinterpret_cast<uint2*>(reinterpret_cast<char*>(g_W) + off) = pk;
        if (c4 == 0) {
            const float* bp = (g == 0) ? bb0 : (g == 1) ? bb1 : (g == 2) ? bb2 : bb3;
            g_bias[n] = bp[hh];
        }
    }
}

// ---------------- fused GEMM + LSTM kernel: bulk-DMA pipeline ----------------
// EXACT R10 mainloop (rotating inline producer, 8 consumer warps 4Mx2N, 32x64
// tiles, 3-stage bulk-DMA). ONLY change vs R10: register-resident shfl
// epilogue (no SMEM staging, no epilogue barriers, per-warp early start).
__global__ void __launch_bounds__(256, 2) lstm_gemm_kernel(const float* __restrict__ c_prev,
                                                           float* __restrict__ out) {
    extern __shared__ char smem[];
    const uint32_t sbase = smem_u32(smem);
    float* bias_sm = reinterpret_cast<float*>(smem);             // 512 B

    const int tid  = threadIdx.x;
    const int wid  = tid >> 5;
    const int lane = tid & 31;
    const int m0 = blockIdx.y * BM;
    const int n0 = blockIdx.x * BN;

    const uint32_t mb = sbase + 512;
    auto full_b  = [&](int s) { return mb + s * 16; };
    auto empty_b = [&](int s) { return mb + s * 16 + 8; };

    if (tid == 0) {
        for (int s = 0; s < STAGES; s++) {
            mbar_init(full_b(s), 1);    // producer's expect_tx arrival
            mbar_init(empty_b(s), 8);   // one arrive per consumer warp
        }
        asm volatile("fence.proxy.async.shared::cta;" ::: "memory");
    }
    if (tid < BN) bias_sm[tid] = g_bias[n0 + tid];
    __syncthreads();

    const char* Abase = reinterpret_cast<const char*>(g_A)
                      + (size_t)blockIdx.y * KITERS * TILE_BYTES;
    const char* Bbase = reinterpret_cast<const char*>(g_W)
                      + (size_t)blockIdx.x * KITERS * TILE_BYTES;

    auto produce = [&](int kp) {      // exactly one thread calls per kp
        const int s2 = kp % STAGES;
        mbar_expect_tx(full_b(s2), STAGE_BYTES);
        const uint32_t a_s = sbase + SMEM_CTRL + s2 * STAGE_BYTES;
        bulk_ldgsts(a_s,              Abase + (size_t)kp * TILE_BYTES, TILE_BYTES, full_b(s2));
        bulk_ldgsts(a_s + TILE_BYTES, Bbase + (size_t)kp * TILE_BYTES, TILE_BYTES, full_b(s2));
    };

    if (tid == 0) { produce(0); produce(1); }   // stages 0,1 known-empty

    // consumer setup
    const int warp_m = wid & 3;
    const int warp_n = wid >> 2;
    const int lrow  = lane & 15;
    const int lkoff = (lane >> 4) * 16;

    uint32_t aoff[2], boff[4];
#pragma unroll
    for (int mt = 0; mt < 2; mt++)
        aoff[mt] = swz128((warp_m * 32 + mt * 16 + lrow) * 128 + lkoff);
#pragma unroll
    for (int nt2 = 0; nt2 < 4; nt2++)
        boff[nt2] = swz128((warp_n * 64 + nt2 * 16 + lrow) * 128 + lkoff);

    float acc[2][8][4];
#pragma unroll
    for (int mt = 0; mt < 2; mt++)
#pragma unroll
        for (int nt = 0; nt < 8; nt++)
#pragma unroll
            for (int q = 0; q < 4; q++) acc[mt][nt][q] = 0.f;

    int s = 0; uint32_t phf = 0;
    for (int k = 0; k < KITERS; k++) {
        // rotating producer: warp (k&7), lane 0
        if (lane == 0 && wid == (k & 7)) {
            const int kp = k + 2;
            if (kp < KITERS) {
                if (kp >= STAGES)   // refill: wait consumers done with previous use
                    mbar_wait(empty_b(kp % STAGES), ((kp / STAGES) + 1) & 1);
                produce(kp);
            }
        }
        mbar_wait(full_b(s), phf);
        const uint32_t a_s = sbase + SMEM_CTRL + s * STAGE_BYTES;
        const uint32_t b_s = a_s + TILE_BYTES;
#pragma unroll
        for (int ks = 0; ks < 4; ks++) {
            const uint32_t kx = ks * 32;
            uint32_t af[2][4];
#pragma unroll
            for (int mt = 0; mt < 2; mt++) ldsm4(af[mt], a_s + (aoff[mt] ^ kx));
            uint32_t bf[4][4];
#pragma unroll
            for (int nt2 = 0; nt2 < 4; nt2++) ldsm4(bf[nt2], b_s + (boff[nt2] ^ kx));
#pragma unroll
            for (int mt = 0; mt < 2; mt++)
#pragma unroll
                for (int nt = 0; nt < 8; nt++)
                    mma16816(acc[mt][nt], af[mt],
                             bf[nt >> 1][nt & 1], bf[nt >> 1][2 + (nt & 1)]);
        }
        if (lane == 0) mbar_arrive(empty_b(s));   // LDSM data is in registers
        if (++s == STAGES) { s = 0; phf ^= 1; }
    }

    // -------- register-resident LSTM epilogue (shfl gate exchange, per-warp) --------
    // m16n8k16 fragment: lane holds c0,c1 = row g4 cols {2t4, 2t4+1}; c2,c3 = row
    // g4+8 same cols. Even t4 -> (gi,gf) of unit u; odd t4 -> (gc,go) of same unit.
    // Partner lane^1 exchange; even lane emits row g4, odd lane emits row g4+8.
    const int g4  = lane >> 2;
    const int t4  = lane & 3;
    const int odd = lane & 1;
    float* h_out = out;
    float* c_out = out + (size_t)BATCH * HID;
    const int h0 = n0 >> 2;
#pragma unroll
    for (int mt = 0; mt < 2; mt++) {
        const int m = m0 + warp_m * 32 + mt * 16 + g4 + odd * 8;
#pragma unroll
        for (int nt = 0; nt < 8; nt++) {
            float* a = acc[mt][nt];
            float s0 = __shfl_xor_sync(0xffffffffu, a[0], 1);
            float s1 = __shfl_xor_sync(0xffffffffu, a[1], 1);
            float s2 = __shfl_xor_sync(0xffffffffu, a[2], 1);
            float s3 = __shfl_xor_sync(0xffffffffu, a[3], 1);
            float gi = odd ? s2   : a[0];
            float gf = odd ? s3   : a[1];
            float gc = odd ? a[2] : s0;
            float go = odd ? a[3] : s1;
            const int ul = warp_n * 16 + nt * 2 + (t4 >> 1);   // unit within CTA (0..31)
            float4 bv = *reinterpret_cast<float4*>(&bias_sm[4 * ul]);
            float it_g = sigmoidf_(gi + bv.x);
            float ft   = sigmoidf_(gf + bv.y);
            float gt   = tanhf_(gc + bv.z);
            float ot   = sigmoidf_(go + bv.w);
            const int hidx = h0 + ul;
            float ct = ft * c_prev[(size_t)m * HID + hidx] + it_g * gt;
            h_out[(size_t)m * HID + hidx] = ot * tanhf_(ct);
            c_out[(size_t)m * HID + hidx] = ct;
        }
    }
}

// ---------------- launch ----------------
extern "C" void kernel_launch(void* const* d_in, const int* in_sizes, int n_in,
                              void* d_out, int out_size) {
    const float* x_t    = (const float*)d_in[0];
    const float* h_prev = (const float*)d_in[1];
    const float* c_prev = (const float*)d_in[2];
    const float* W_i = (const float*)d_in[3];
    const float* b_i = (const float*)d_in[4];
    const float* W_f = (const float*)d_in[5];
    const float* b_f = (const float*)d_in[6];
    const float* W_c = (const float*)d_in[7];
    const float* b_c = (const float*)d_in[8];
    const float* W_o = (const float*)d_in[9];
    const float* b_o = (const float*)d_in[10];
    float* out = (float*)d_out;

    cudaFuncSetAttribute(lstm_gemm_kernel,
                         cudaFuncAttributeMaxDynamicSharedMemorySize, SMEM_TOTAL);

    convert_all_kernel<<<(TOT_CHUNKS + 255) / 256, 256>>>(
        x_t, h_prev, W_i, W_f, W_c, W_o, b_i, b_f, b_c, b_o);
    dim3 grid(NDIM / BN, BATCH / BM);  // 64 x 32
    lstm_gemm_kernel<<<grid, 256, SMEM_TOTAL>>>(c_prev, out);
}

// round 15
// speedup vs baseline: 1.6326x; 1.0033x over previous
#include <cuda_runtime.h>
#include <cuda_fp16.h>
#include <cstdint>

// ---------------- problem constants ----------------
static constexpr int BATCH = 4096;
static constexpr int IN_SZ = 1024;
static constexpr int HID   = 2048;
static constexpr int KDIM  = 3072;   // IN_SZ + HID
static constexpr int NDIM  = 8192;   // 4*HID, gate-interleaved rows: n = 4*h + gate

// ---------------- GEMM tiling ----------------
static constexpr int BM = 128;
static constexpr int BN = 128;
static constexpr int BK = 64;
static constexpr int KITERS = KDIM / BK;     // 48
static constexpr int STAGES = 3;
static constexpr int TILE_BYTES = 128 * 64 * 2;       // 16 KB
static constexpr int STAGE_BYTES = 2 * TILE_BYTES;    // 32 KB
static constexpr int SMEM_CTRL = 1024;
static constexpr int SMEM_TOTAL = SMEM_CTRL + STAGES * STAGE_BYTES;  // 99328

// ---------------- device scratch: PRE-TILED + PRE-SWIZZLED ----------------
__device__ __align__(1024) __half g_A[(size_t)BATCH * KDIM];   // 25 MB
__device__ __align__(1024) __half g_W[(size_t)NDIM * KDIM];    // 50 MB
__device__ float  g_bias[NDIM];

// ---------------- helpers ----------------
__device__ __forceinline__ uint32_t smem_u32(const void* p) {
    uint32_t a;
    asm("{ .reg .u64 t; cvta.to.shared.u64 t, %1; cvt.u32.u64 %0, t; }" : "=r"(a) : "l"(p));
    return a;
}
__device__ __forceinline__ uint32_t swz128(uint32_t off) {
    return off ^ ((off >> 3) & 0x70);
}
__device__ __forceinline__ void mbar_init(uint32_t a, uint32_t cnt) {
    asm volatile("mbarrier.init.shared.b64 [%0], %1;" :: "r"(a), "r"(cnt) : "memory");
}
__device__ __forceinline__ void mbar_arrive(uint32_t a) {
    asm volatile("mbarrier.arrive.shared.b64 _, [%0];" :: "r"(a) : "memory");
}
__device__ __forceinline__ void mbar_expect_tx(uint32_t a, uint32_t bytes) {
    asm volatile("mbarrier.arrive.expect_tx.shared.b64 _, [%0], %1;"
                 :: "r"(a), "r"(bytes) : "memory");
}
__device__ __forceinline__ void mbar_wait(uint32_t mbar, uint32_t parity) {
    uint32_t done;
    do {
        asm volatile("{\n\t.reg .pred p;\n\t"
            "mbarrier.try_wait.parity.acquire.cta.shared::cta.b64 p, [%1], %2, 0x989680;\n\t"
            "selp.b32 %0, 1, 0, p;\n\t}"
            : "=r"(done) : "r"(mbar), "r"(parity) : "memory");
    } while (!done);
}
__device__ __forceinline__ void bulk_ldgsts(uint32_t dst, const void* src,
                                            uint32_t bytes, uint32_t mbar) {
    asm volatile("cp.async.bulk.shared::cluster.global.mbarrier::complete_tx::bytes "
                 "[%0], [%1], %2, [%3];"
                 :: "r"(dst), "l"(src), "r"(bytes), "r"(mbar) : "memory");
}
__device__ __forceinline__ void ldsm4(uint32_t* r, uint32_t addr) {
    asm volatile("ldmatrix.sync.aligned.m8n8.x4.shared.b16 {%0,%1,%2,%3}, [%4];"
                 : "=r"(r[0]), "=r"(r[1]), "=r"(r[2]), "=r"(r[3]) : "r"(addr));
}
__device__ __forceinline__ void mma16816(float* c, const uint32_t* a, uint32_t b0, uint32_t b1) {
    asm volatile("mma.sync.aligned.m16n8k16.row.col.f32.f16.f16.f32 "
                 "{%0,%1,%2,%3}, {%4,%5,%6,%7}, {%8,%9}, {%0,%1,%2,%3};"
                 : "+f"(c[0]), "+f"(c[1]), "+f"(c[2]), "+f"(c[3])
                 : "r"(a[0]), "r"(a[1]), "r"(a[2]), "r"(a[3]), "r"(b0), "r"(b1));
}
__device__ __forceinline__ float sigmoidf_(float x) { return 1.f / (1.f + __expf(-x)); }
__device__ __forceinline__ float tanhf_(float x)    { return 2.f / (1.f + __expf(-2.f * x)) - 1.f; }

// ---------------- merged conversion: 16B output granules ----------------
// Each thread converts 8 consecutive halves: 2x float4 load -> 1x uint4 store
// at the 16B-aligned swizzled offset (swz128 preserves 16B alignment).
static constexpr int A_CH16 = BATCH * KDIM / 8;   // 1.57M
static constexpr int W_CH16 = NDIM * KDIM / 8;    // 3.15M
static constexpr int TOT_CH16 = A_CH16 + W_CH16;

__device__ __forceinline__ uint4 pack8(float4 v0, float4 v1) {
    __half2 h0 = __floats2half2_rn(v0.x, v0.y);
    __half2 h1 = __floats2half2_rn(v0.z, v0.w);
    __half2 h2 = __floats2half2_rn(v1.x, v1.y);
    __half2 h3 = __floats2half2_rn(v1.z, v1.w);
    uint4 r;
    r.x = *reinterpret_cast<uint32_t*>(&h0);
    r.y = *reinterpret_cast<uint32_t*>(&h1);
    r.z = *reinterpret_cast<uint32_t*>(&h2);
    r.w = *reinterpret_cast<uint32_t*>(&h3);
    return r;
}

__global__ void __launch_bounds__(256) convert_all_kernel(
    const float* __restrict__ x, const float* __restrict__ h,
    const float* __restrict__ W0, const float* __restrict__ W1,
    const float* __restrict__ W2, const float* __restrict__ W3,
    const float* __restrict__ bb0, const float* __restrict__ bb1,
    const float* __restrict__ bb2, const float* __restrict__ bb3) {
    int idx = blockIdx.x * blockDim.x + threadIdx.x;
    if (idx >= TOT_CH16) return;
    if (idx < A_CH16) {
        int b   = idx / (KDIM / 8);
        int col = (idx - b * (KDIM / 8)) * 8;
        float4 v0, v1;
        if (col < IN_SZ) {           // IN_SZ multiple of 8: no straddle
            v0 = *(const float4*)(x + (size_t)b * IN_SZ + col);
            v1 = *(const float4*)(x + (size_t)b * IN_SZ + col + 4);
        } else {
            v0 = *(const float4*)(h + (size_t)b * HID + (col - IN_SZ));
            v1 = *(const float4*)(h + (size_t)b * HID + (col - IN_SZ) + 4);
        }
        int tm = b >> 7, row = b & 127;
        int kt = col >> 6, c = col & 63;
        size_t off = (size_t)(tm * KITERS + kt) * TILE_BYTES + swz128(row * 128 + c * 2);
        *reinterpret_cast<uint4*>(reinterpret_cast<char*>(g_A) + off) = pack8(v0, v1);
    } else {
        int widx = idx - A_CH16;
        int n   = widx / (KDIM / 8);
        int c8  = widx - n * (KDIM / 8);
        int col = c8 * 8;
        int g = n & 3, hh = n >> 2;
        const float* W = (g == 0) ? W0 : (g == 1) ? W1 : (g == 2) ? W2 : W3;
        float4 v0 = *(const float4*)(W + (size_t)hh * KDIM + col);
        float4 v1 = *(const float4*)(W + (size_t)hh * KDIM + col + 4);
        int tn = n >> 7, row = n & 127;
        int kt = col >> 6, c = col & 63;
        size_t off = (size_t)(tn * KITERS + kt) * TILE_BYTES + swz128(row * 128 + c * 2);
        *reinterpret_cast<uint4*>(reinterpret_cast<char*>(g_W) + off) = pack8(v0, v1);
        if (c8 == 0) {
            const float* bp = (g == 0) ? bb0 : (g == 1) ? bb1 : (g == 2) ? bb2 : bb3;
            g_bias[n] = bp[hh];
        }
    }
}

// ---------------- fused GEMM + LSTM kernel: bulk-DMA pipeline ----------------
// R14 core. ONLY mainloop change: per-warp ks-rotation ((j+wid)&3) to break the
// post-full-wait phase-lock (all warps bursting LDSM simultaneously).
__global__ void __launch_bounds__(256, 2) lstm_gemm_kernel(const float* __restrict__ c_prev,
                                                           float* __restrict__ out) {
    extern __shared__ char smem[];
    const uint32_t sbase = smem_u32(smem);
    float* bias_sm = reinterpret_cast<float*>(smem);             // 512 B

    const int tid  = threadIdx.x;
    const int wid  = tid >> 5;
    const int lane = tid & 31;
    const int m0 = blockIdx.y * BM;
    const int n0 = blockIdx.x * BN;

    const uint32_t mb = sbase + 512;
    auto full_b  = [&](int s) { return mb + s * 16; };
    auto empty_b = [&](int s) { return mb + s * 16 + 8; };

    if (tid == 0) {
        for (int s = 0; s < STAGES; s++) {
            mbar_init(full_b(s), 1);    // producer's expect_tx arrival
            mbar_init(empty_b(s), 8);   // one arrive per consumer warp
        }
        asm volatile("fence.proxy.async.shared::cta;" ::: "memory");
    }
    if (tid < BN) bias_sm[tid] = g_bias[n0 + tid];
    __syncthreads();

    const char* Abase = reinterpret_cast<const char*>(g_A)
                      + (size_t)blockIdx.y * KITERS * TILE_BYTES;
    const char* Bbase = reinterpret_cast<const char*>(g_W)
                      + (size_t)blockIdx.x * KITERS * TILE_BYTES;

    auto produce = [&](int kp) {      // exactly one thread calls per kp
        const int s2 = kp % STAGES;
        mbar_expect_tx(full_b(s2), STAGE_BYTES);
        const uint32_t a_s = sbase + SMEM_CTRL + s2 * STAGE_BYTES;
        bulk_ldgsts(a_s,              Abase + (size_t)kp * TILE_BYTES, TILE_BYTES, full_b(s2));
        bulk_ldgsts(a_s + TILE_BYTES, Bbase + (size_t)kp * TILE_BYTES, TILE_BYTES, full_b(s2));
    };

    if (tid == 0) { produce(0); produce(1); }   // stages 0,1 known-empty

    // consumer setup
    const int warp_m = wid & 3;
    const int warp_n = wid >> 2;
    const int lrow  = lane & 15;
    const int lkoff = (lane >> 4) * 16;

    uint32_t aoff[2], boff[4];
#pragma unroll
    for (int mt = 0; mt < 2; mt++)
        aoff[mt] = swz128((warp_m * 32 + mt * 16 + lrow) * 128 + lkoff);
#pragma unroll
    for (int nt2 = 0; nt2 < 4; nt2++)
        boff[nt2] = swz128((warp_n * 64 + nt2 * 16 + lrow) * 128 + lkoff);

    float acc[2][8][4];
#pragma unroll
    for (int mt = 0; mt < 2; mt++)
#pragma unroll
        for (int nt = 0; nt < 8; nt++)
#pragma unroll
            for (int q = 0; q < 4; q++) acc[mt][nt][q] = 0.f;

    int s = 0; uint32_t phf = 0;
    for (int k = 0; k < KITERS; k++) {
        // rotating producer: warp (k&7), lane 0
        if (lane == 0 && wid == (k & 7)) {
            const int kp = k + 2;
            if (kp < KITERS) {
                if (kp >= STAGES)   // refill: wait consumers done with previous use
                    mbar_wait(empty_b(kp % STAGES), ((kp / STAGES) + 1) & 1);
                produce(kp);
            }
        }
        mbar_wait(full_b(s), phf);
        const uint32_t a_s = sbase + SMEM_CTRL + s * STAGE_BYTES;
        const uint32_t b_s = a_s + TILE_BYTES;
#pragma unroll
        for (int j = 0; j < 4; j++) {
            const int ks = (j + wid) & 3;      // per-warp rotation: de-phase-lock LDSM bursts
            const uint32_t kx = ks * 32;
            uint32_t af[2][4];
#pragma unroll
            for (int mt = 0; mt < 2; mt++) ldsm4(af[mt], a_s + (aoff[mt] ^ kx));
            uint32_t bf[4][4];
#pragma unroll
            for (int nt2 = 0; nt2 < 4; nt2++) ldsm4(bf[nt2], b_s + (boff[nt2] ^ kx));
#pragma unroll
            for (int mt = 0; mt < 2; mt++)
#pragma unroll
                for (int nt = 0; nt < 8; nt++)
                    mma16816(acc[mt][nt], af[mt],
                             bf[nt >> 1][nt & 1], bf[nt >> 1][2 + (nt & 1)]);
        }
        if (lane == 0) mbar_arrive(empty_b(s));   // LDSM data is in registers
        if (++s == STAGES) { s = 0; phf ^= 1; }
    }

    // -------- register-resident LSTM epilogue (shfl gate exchange, per-warp) --------
    const int g4  = lane >> 2;
    const int t4  = lane & 3;
    const int odd = lane & 1;
    float* h_out = out;
    float* c_out = out + (size_t)BATCH * HID;
    const int h0 = n0 >> 2;
#pragma unroll
    for (int mt = 0; mt < 2; mt++) {
        const int m = m0 + warp_m * 32 + mt * 16 + g4 + odd * 8;
#pragma unroll
        for (int nt = 0; nt < 8; nt++) {
            float* a = acc[mt][nt];
            float s0 = __shfl_xor_sync(0xffffffffu, a[0], 1);
            float s1 = __shfl_xor_sync(0xffffffffu, a[1], 1);
            float s2 = __shfl_xor_sync(0xffffffffu, a[2], 1);
            float s3 = __shfl_xor_sync(0xffffffffu, a[3], 1);
            float gi = odd ? s2   : a[0];
            float gf = odd ? s3   : a[1];
            float gc = odd ? a[2] : s0;
            float go = odd ? a[3] : s1;
            const int ul = warp_n * 16 + nt * 2 + (t4 >> 1);   // unit within CTA (0..31)
            float4 bv = *reinterpret_cast<float4*>(&bias_sm[4 * ul]);
            float it_g = sigmoidf_(gi + bv.x);
            float ft   = sigmoidf_(gf + bv.y);
            float gt   = tanhf_(gc + bv.z);
            float ot   = sigmoidf_(go + bv.w);
            const int hidx = h0 + ul;
            float ct = ft * c_prev[(size_t)m * HID + hidx] + it_g * gt;
            h_out[(size_t)m * HID + hidx] = ot * tanhf_(ct);
            c_out[(size_t)m * HID + hidx] = ct;
        }
    }
}

// ---------------- launch ----------------
extern "C" void kernel_launch(void* const* d_in, const int* in_sizes, int n_in,
                              void* d_out, int out_size) {
    const float* x_t    = (const float*)d_in[0];
    const float* h_prev = (const float*)d_in[1];
    const float* c_prev = (const float*)d_in[2];
    const float* W_i = (const float*)d_in[3];
    const float* b_i = (const float*)d_in[4];
    const float* W_f = (const float*)d_in[5];
    const float* b_f = (const float*)d_in[6];
    const float* W_c = (const float*)d_in[7];
    const float* b_c = (const float*)d_in[8];
    const float* W_o = (const float*)d_in[9];
    const float* b_o = (const float*)d_in[10];
    float* out = (float*)d_out;

    cudaFuncSetAttribute(lstm_gemm_kernel,
                         cudaFuncAttributeMaxDynamicSharedMemorySize, SMEM_TOTAL);

    convert_all_kernel<<<(TOT_CH16 + 255) / 256, 256>>>(
        x_t, h_prev, W_i, W_f, W_c, W_o, b_i, b_f, b_c, b_o);
    dim3 grid(NDIM / BN, BATCH / BM);  // 64 x 32
    lstm_gemm_kernel<<<grid, 256, SMEM_TOTAL>>>(c_prev, out);
}

// round 16
// speedup vs baseline: 1.6493x; 1.0102x over previous
#include <cuda_runtime.h>
#include <cuda_fp16.h>
#include <cstdint>

// ---------------- problem constants ----------------
static constexpr int BATCH = 4096;
static constexpr int IN_SZ = 1024;
static constexpr int HID   = 2048;
static constexpr int KDIM  = 3072;   // IN_SZ + HID
static constexpr int NDIM  = 8192;   // 4*HID, gate-interleaved rows: n = 4*h + gate

// ---------------- GEMM tiling ----------------
static constexpr int BM = 128;
static constexpr int BN = 128;
static constexpr int BK = 64;
static constexpr int KITERS = KDIM / BK;     // 48
static constexpr int STAGES = 3;
static constexpr int TILE_BYTES = 128 * 64 * 2;       // 16 KB
static constexpr int STAGE_BYTES = 2 * TILE_BYTES;    // 32 KB
static constexpr int SMEM_CTRL = 1024;
static constexpr int SMEM_TOTAL = SMEM_CTRL + STAGES * STAGE_BYTES;  // 99328

// ---------------- device scratch: PRE-TILED + PRE-SWIZZLED ----------------
__device__ __align__(1024) __half g_A[(size_t)BATCH * KDIM];   // 25 MB
__device__ __align__(1024) __half g_W[(size_t)NDIM * KDIM];    // 50 MB
__device__ float  g_bias[NDIM];

// ---------------- helpers ----------------
__device__ __forceinline__ uint32_t smem_u32(const void* p) {
    uint32_t a;
    asm("{ .reg .u64 t; cvta.to.shared.u64 t, %1; cvt.u32.u64 %0, t; }" : "=r"(a) : "l"(p));
    return a;
}
__device__ __forceinline__ uint32_t swz128(uint32_t off) {
    return off ^ ((off >> 3) & 0x70);
}
__device__ __forceinline__ void mbar_init(uint32_t a, uint32_t cnt) {
    asm volatile("mbarrier.init.shared.b64 [%0], %1;" :: "r"(a), "r"(cnt) : "memory");
}
__device__ __forceinline__ void mbar_arrive(uint32_t a) {
    asm volatile("mbarrier.arrive.shared.b64 _, [%0];" :: "r"(a) : "memory");
}
__device__ __forceinline__ void mbar_expect_tx(uint32_t a, uint32_t bytes) {
    asm volatile("mbarrier.arrive.expect_tx.shared.b64 _, [%0], %1;"
                 :: "r"(a), "r"(bytes) : "memory");
}
__device__ __forceinline__ void mbar_wait(uint32_t mbar, uint32_t parity) {
    uint32_t done;
    do {
        asm volatile("{\n\t.reg .pred p;\n\t"
            "mbarrier.try_wait.parity.acquire.cta.shared::cta.b64 p, [%1], %2, 0x989680;\n\t"
            "selp.b32 %0, 1, 0, p;\n\t}"
            : "=r"(done) : "r"(mbar), "r"(parity) : "memory");
    } while (!done);
}
// relaxed variant: producer-only (post-wait accesses are all async-proxy)
__device__ __forceinline__ void mbar_wait_relaxed(uint32_t mbar, uint32_t parity) {
    uint32_t done;
    do {
        asm volatile("{\n\t.reg .pred p;\n\t"
            "mbarrier.try_wait.parity.relaxed.cta.shared::cta.b64 p, [%1], %2, 0x989680;\n\t"
            "selp.b32 %0, 1, 0, p;\n\t}"
            : "=r"(done) : "r"(mbar), "r"(parity) : "memory");
    } while (!done);
}
__device__ __forceinline__ void bulk_ldgsts(uint32_t dst, const void* src,
                                            uint32_t bytes, uint32_t mbar) {
    asm volatile("cp.async.bulk.shared::cluster.global.mbarrier::complete_tx::bytes "
                 "[%0], [%1], %2, [%3];"
                 :: "r"(dst), "l"(src), "r"(bytes), "r"(mbar) : "memory");
}
__device__ __forceinline__ void ldsm4(uint32_t* r, uint32_t addr) {
    asm volatile("ldmatrix.sync.aligned.m8n8.x4.shared.b16 {%0,%1,%2,%3}, [%4];"
                 : "=r"(r[0]), "=r"(r[1]), "=r"(r[2]), "=r"(r[3]) : "r"(addr));
}
__device__ __forceinline__ void mma16816(float* c, const uint32_t* a, uint32_t b0, uint32_t b1) {
    asm volatile("mma.sync.aligned.m16n8k16.row.col.f32.f16.f16.f32 "
                 "{%0,%1,%2,%3}, {%4,%5,%6,%7}, {%8,%9}, {%0,%1,%2,%3};"
                 : "+f"(c[0]), "+f"(c[1]), "+f"(c[2]), "+f"(c[3])
                 : "r"(a[0]), "r"(a[1]), "r"(a[2]), "r"(a[3]), "r"(b0), "r"(b1));
}
__device__ __forceinline__ float sigmoidf_(float x) { return 1.f / (1.f + __expf(-x)); }
__device__ __forceinline__ float tanhf_(float x)    { return 2.f / (1.f + __expf(-2.f * x)) - 1.f; }

// ---------------- merged conversion: 16B output granules (R15, best measured) ----------------
static constexpr int A_CH16 = BATCH * KDIM / 8;   // 1.57M
static constexpr int W_CH16 = NDIM * KDIM / 8;    // 3.15M
static constexpr int TOT_CH16 = A_CH16 + W_CH16;

__device__ __forceinline__ uint4 pack8(float4 v0, float4 v1) {
    __half2 h0 = __floats2half2_rn(v0.x, v0.y);
    __half2 h1 = __floats2half2_rn(v0.z, v0.w);
    __half2 h2 = __floats2half2_rn(v1.x, v1.y);
    __half2 h3 = __floats2half2_rn(v1.z, v1.w);
    uint4 r;
    r.x = *reinterpret_cast<uint32_t*>(&h0);
    r.y = *reinterpret_cast<uint32_t*>(&h1);
    r.z = *reinterpret_cast<uint32_t*>(&h2);
    r.w = *reinterpret_cast<uint32_t*>(&h3);
    return r;
}

__global__ void __launch_bounds__(256) convert_all_kernel(
    const float* __restrict__ x, const float* __restrict__ h,
    const float* __restrict__ W0, const float* __restrict__ W1,
    const float* __restrict__ W2, const float* __restrict__ W3,
    const float* __restrict__ bb0, const float* __restrict__ bb1,
    const float* __restrict__ bb2, const float* __restrict__ bb3) {
    int idx = blockIdx.x * blockDim.x + threadIdx.x;
    if (idx >= TOT_CH16) return;
    if (idx < A_CH16) {
        int b   = idx / (KDIM / 8);
        int col = (idx - b * (KDIM / 8)) * 8;
        float4 v0, v1;
        if (col < IN_SZ) {           // IN_SZ multiple of 8: no straddle
            v0 = *(const float4*)(x + (size_t)b * IN_SZ + col);
            v1 = *(const float4*)(x + (size_t)b * IN_SZ + col + 4);
        } else {
            v0 = *(const float4*)(h + (size_t)b * HID + (col - IN_SZ));
            v1 = *(const float4*)(h + (size_t)b * HID + (col - IN_SZ) + 4);
        }
        int tm = b >> 7, row = b & 127;
        int kt = col >> 6, c = col & 63;
        size_t off = (size_t)(tm * KITERS + kt) * TILE_BYTES + swz128(row * 128 + c * 2);
        *reinterpret_cast<uint4*>(reinterpret_cast<char*>(g_A) + off) = pack8(v0, v1);
    } else {
        int widx = idx - A_CH16;
        int n   = widx / (KDIM / 8);
        int c8  = widx - n * (KDIM / 8);
        int col = c8 * 8;
        int g = n & 3, hh = n >> 2;
        const float* W = (g == 0) ? W0 : (g == 1) ? W1 : (g == 2) ? W2 : W3;
        float4 v0 = *(const float4*)(W + (size_t)hh * KDIM + col);
        float4 v1 = *(const float4*)(W + (size_t)hh * KDIM + col + 4);
        int tn = n >> 7, row = n & 127;
        int kt = col >> 6, c = col & 63;
        size_t off = (size_t)(tn * KITERS + kt) * TILE_BYTES + swz128(row * 128 + c * 2);
        *reinterpret_cast<uint4*>(reinterpret_cast<char*>(g_W) + off) = pack8(v0, v1);
        if (c8 == 0) {
            const float* bp = (g == 0) ? bb0 : (g == 1) ? bb1 : (g == 2) ? bb2 : bb3;
            g_bias[n] = bp[hh];
        }
    }
}

// ---------------- fused GEMM + LSTM kernel: bulk-DMA pipeline ----------------
// EXACT R14 mainloop (best measured GEMM: sequential ks, rotating inline
// producer, 8 consumer warps 4Mx2N 32x64, 3-stage bulk-DMA, shfl epilogue).
// Only producer-side tweak: relaxed empty-wait (post-wait ops are async-proxy).
__global__ void __launch_bounds__(256, 2) lstm_gemm_kernel(const float* __restrict__ c_prev,
                                                           float* __restrict__ out) {
    extern __shared__ char smem[];
    const uint32_t sbase = smem_u32(smem);
    float* bias_sm = reinterpret_cast<float*>(smem);             // 512 B

    const int tid  = threadIdx.x;
    const int wid  = tid >> 5;
    const int lane = tid & 31;
    const int m0 = blockIdx.y * BM;
    const int n0 = blockIdx.x * BN;

    const uint32_t mb = sbase + 512;
    auto full_b  = [&](int s) { return mb + s * 16; };
    auto empty_b = [&](int s) { return mb + s * 16 + 8; };

    if (tid == 0) {
        for (int s = 0; s < STAGES; s++) {
            mbar_init(full_b(s), 1);    // producer's expect_tx arrival
            mbar_init(empty_b(s), 8);   // one arrive per consumer warp
        }
        asm volatile("fence.proxy.async.shared::cta;" ::: "memory");
    }
    if (tid < BN) bias_sm[tid] = g_bias[n0 + tid];
    __syncthreads();

    const char* Abase = reinterpret_cast<const char*>(g_A)
                      + (size_t)blockIdx.y * KITERS * TILE_BYTES;
    const char* Bbase = reinterpret_cast<const char*>(g_W)
                      + (size_t)blockIdx.x * KITERS * TILE_BYTES;

    auto produce = [&](int kp) {      // exactly one thread calls per kp
        const int s2 = kp % STAGES;
        mbar_expect_tx(full_b(s2), STAGE_BYTES);
        const uint32_t a_s = sbase + SMEM_CTRL + s2 * STAGE_BYTES;
        bulk_ldgsts(a_s,              Abase + (size_t)kp * TILE_BYTES, TILE_BYTES, full_b(s2));
        bulk_ldgsts(a_s + TILE_BYTES, Bbase + (size_t)kp * TILE_BYTES, TILE_BYTES, full_b(s2));
    };

    if (tid == 0) { produce(0); produce(1); }   // stages 0,1 known-empty

    // consumer setup
    const int warp_m = wid & 3;
    const int warp_n = wid >> 2;
    const int lrow  = lane & 15;
    const int lkoff = (lane >> 4) * 16;

    uint32_t aoff[2], boff[4];
#pragma unroll
    for (int mt = 0; mt < 2; mt++)
        aoff[mt] = swz128((warp_m * 32 + mt * 16 + lrow) * 128 + lkoff);
#pragma unroll
    for (int nt2 = 0; nt2 < 4; nt2++)
        boff[nt2] = swz128((warp_n * 64 + nt2 * 16 + lrow) * 128 + lkoff);

    float acc[2][8][4];
#pragma unroll
    for (int mt = 0; mt < 2; mt++)
#pragma unroll
        for (int nt = 0; nt < 8; nt++)
#pragma unroll
            for (int q = 0; q < 4; q++) acc[mt][nt][q] = 0.f;

    int s = 0; uint32_t phf = 0;
    for (int k = 0; k < KITERS; k++) {
        // rotating producer: warp (k&7), lane 0
        if (lane == 0 && wid == (k & 7)) {
            const int kp = k + 2;
            if (kp < KITERS) {
                if (kp >= STAGES)   // refill: wait consumers done with previous use
                    mbar_wait_relaxed(empty_b(kp % STAGES), ((kp / STAGES) + 1) & 1);
                produce(kp);
            }
        }
        mbar_wait(full_b(s), phf);
        const uint32_t a_s = sbase + SMEM_CTRL + s * STAGE_BYTES;
        const uint32_t b_s = a_s + TILE_BYTES;
#pragma unroll
        for (int ks = 0; ks < 4; ks++) {
            const uint32_t kx = ks * 32;
            uint32_t af[2][4];
#pragma unroll
            for (int mt = 0; mt < 2; mt++) ldsm4(af[mt], a_s + (aoff[mt] ^ kx));
            uint32_t bf[4][4];
#pragma unroll
            for (int nt2 = 0; nt2 < 4; nt2++) ldsm4(bf[nt2], b_s + (boff[nt2] ^ kx));
#pragma unroll
            for (int mt = 0; mt < 2; mt++)
#pragma unroll
                for (int nt = 0; nt < 8; nt++)
                    mma16816(acc[mt][nt], af[mt],
                             bf[nt >> 1][nt & 1], bf[nt >> 1][2 + (nt & 1)]);
        }
        if (lane == 0) mbar_arrive(empty_b(s));   // LDSM data is in registers
        if (++s == STAGES) { s = 0; phf ^= 1; }
    }

    // -------- register-resident LSTM epilogue (shfl gate exchange, per-warp) --------
    const int g4  = lane >> 2;
    const int t4  = lane & 3;
    const int odd = lane & 1;
    float* h_out = out;
    float* c_out = out + (size_t)BATCH * HID;
    const int h0 = n0 >> 2;
#pragma unroll
    for (int mt = 0; mt < 2; mt++) {
        const int m = m0 + warp_m * 32 + mt * 16 + g4 + odd * 8;
#pragma unroll
        for (int nt = 0; nt < 8; nt++) {
            float* a = acc[mt][nt];
            float s0 = __shfl_xor_sync(0xffffffffu, a[0], 1);
            float s1 = __shfl_xor_sync(0xffffffffu, a[1], 1);
            float s2 = __shfl_xor_sync(0xffffffffu, a[2], 1);
            float s3 = __shfl_xor_sync(0xffffffffu, a[3], 1);
            float gi = odd ? s2   : a[0];
            float gf = odd ? s3   : a[1];
            float gc = odd ? a[2] : s0;
            float go = odd ? a[3] : s1;
            const int ul = warp_n * 16 + nt * 2 + (t4 >> 1);   // unit within CTA (0..31)
            float4 bv = *reinterpret_cast<float4*>(&bias_sm[4 * ul]);
            float it_g = sigmoidf_(gi + bv.x);
            float ft   = sigmoidf_(gf + bv.y);
            float gt   = tanhf_(gc + bv.z);
            float ot   = sigmoidf_(go + bv.w);
            const int hidx = h0 + ul;
            float ct = ft * c_prev[(size_t)m * HID + hidx] + it_g * gt;
            h_out[(size_t)m * HID + hidx] = ot * tanhf_(ct);
            c_out[(size_t)m * HID + hidx] = ct;
        }
    }
}

// ---------------- launch ----------------
extern "C" void kernel_launch(void* const* d_in, const int* in_sizes, int n_in,
                              void* d_out, int out_size) {
    const float* x_t    = (const float*)d_in[0];
    const float* h_prev = (const float*)d_in[1];
    const float* c_prev = (const float*)d_in[2];
    const float* W_i = (const float*)d_in[3];
    const float* b_i = (const float*)d_in[4];
    const float* W_f = (const float*)d_in[5];
    const float* b_f = (const float*)d_in[6];
    const float* W_c = (const float*)d_in[7];
    const float* b_c = (const float*)d_in[8];
    const float* W_o = (const float*)d_in[9];
    const float* b_o = (const float*)d_in[10];
    float* out = (float*)d_out;

    cudaFuncSetAttribute(lstm_gemm_kernel,
                         cudaFuncAttributeMaxDynamicSharedMemorySize, SMEM_TOTAL);

    convert_all_kernel<<<(TOT_CH16 + 255) / 256, 256>>>(
        x_t, h_prev, W_i, W_f, W_c, W_o, b_i, b_f, b_c, b_o);
    dim3 grid(NDIM / BN, BATCH / BM);  // 64 x 32
    lstm_gemm_kernel<<<grid, 256, SMEM_TOTAL>>>(c_prev, out);
}